// round 11
// baseline (speedup 1.0000x reference)
#include <cuda_runtime.h>
#include <cstdint>
#include <math.h>

// ---------------- problem constants ----------------
#define NGEN 10
#define BSZ  4096
#define INDIM 512
#define DIM  1024
#define MAX_TILES 48

// ---------------- scratch ----------------
__device__ float g_x [BSZ * INDIM];
__device__ float g_s1[BSZ * DIM];
__device__ float g_s2[BSZ * DIM];
__device__ float g_ws1[INDIM * DIM];
__device__ float g_ws2[DIM * DIM];
__device__ float g_we1[NGEN * DIM * DIM];
__device__ float g_we2[NGEN * DIM * DIM];
__device__ int   g_perm[BSZ];
__device__ int   g_tile_genre[MAX_TILES];
__device__ int   g_tile_start[MAX_TILES];
__device__ int   g_tile_rows [MAX_TILES];
__device__ int   g_tile_count;

// ---------------- helpers ----------------
__device__ __forceinline__ unsigned f2tf(float x) {
    unsigned r;
    asm("cvt.rna.tf32.f32 %0, %1;" : "=r"(r) : "f"(x));
    return r;
}
__device__ __forceinline__ float tfr(float x) {
    return __uint_as_float(f2tf(x));
}
__device__ __forceinline__ float gelu_f(float x) {
    return 0.5f * x * (1.0f + erff(x * 0.70710678118654752f));
}

// ---------------- tf32 pre-rounding of weights (4 float4 / thread) ---------
__global__ void round_w(const float4* __restrict__ s, float4* __restrict__ d, int n4) {
    int base = (blockIdx.x * blockDim.x + threadIdx.x) * 4;
#pragma unroll
    for (int j = 0; j < 4; j++) {
        int i = base + j;
        if (i < n4) {
            float4 v = s[i];
            d[i] = make_float4(tfr(v.x), tfr(v.y), tfr(v.z), tfr(v.w));
        }
    }
}

// ---------------- reparameterized sample (tf32-rounded output) -------------
__global__ void noise_kernel(const float4* __restrict__ mu,
                             const float4* __restrict__ sig,
                             const float4* __restrict__ z,
                             const int* __restrict__ genre,
                             float4* __restrict__ x) {
    const int C4 = INDIM / 4;
    int i = blockIdx.x * blockDim.x + threadIdx.x;
    if (i >= BSZ * C4) return;
    int row = i / C4, c = i - row * C4;
    int g = genre[row];
    float4 m = mu[g * C4 + c];
    float4 s = sig[g * C4 + c];
    float4 zz = z[i];
    float4 o;
    o.x = tfr(m.x + (fabsf(s.x) + 1e-8f) * zz.x);
    o.y = tfr(m.y + (fabsf(s.y) + 1e-8f) * zz.y);
    o.z = tfr(m.z + (fabsf(s.z) + 1e-8f) * zz.z);
    o.w = tfr(m.w + (fabsf(s.w) + 1e-8f) * zz.w);
    x[i] = o;
}

// ---------------- grouping (full tiles emitted first, partial last) --------
__global__ void group_kernel(const int* __restrict__ genre) {
    __shared__ int cnt[256 * NGEN];
    __shared__ int tot[NGEN];
    __shared__ int base[NGEN];
    int t = threadIdx.x;
    const int per = BSZ / 256;

    int lc[NGEN];
#pragma unroll
    for (int g = 0; g < NGEN; g++) lc[g] = 0;
    int gr[per];
    for (int i = 0; i < per; i++) {
        int g = genre[t * per + i];
        gr[i] = g;
        lc[g]++;
    }
    for (int g = 0; g < NGEN; g++) cnt[t * NGEN + g] = lc[g];
    __syncthreads();

    if (t < NGEN) {
        int s = 0;
        for (int tt = 0; tt < 256; tt++) {
            int v = cnt[tt * NGEN + t];
            cnt[tt * NGEN + t] = s;
            s += v;
        }
        tot[t] = s;
    }
    __syncthreads();

    if (t == 0) {
        int off = 0;
        for (int g = 0; g < NGEN; g++) { base[g] = off; off += tot[g]; }
        int T = 0;
        int prows[NGEN], pstart[NGEN];
        // full tiles first (wave 1 of the expert launch)
        for (int g = 0; g < NGEN; g++) {
            int c = tot[g], s0 = base[g];
            while (c >= 128) {
                g_tile_genre[T] = g;
                g_tile_start[T] = s0;
                g_tile_rows[T]  = 128;
                s0 += 128; c -= 128; T++;
            }
            prows[g] = c; pstart[g] = s0;
        }
        // partial tiles last (cheap wave 2)
        for (int g = 0; g < NGEN; g++) {
            if (prows[g] > 0) {
                g_tile_genre[T] = g;
                g_tile_start[T] = pstart[g];
                g_tile_rows[T]  = prows[g];
                T++;
            }
        }
        g_tile_count = T;
    }
    __syncthreads();

    int run[NGEN];
#pragma unroll
    for (int g = 0; g < NGEN; g++) run[g] = cnt[t * NGEN + g];
    for (int i = 0; i < per; i++) {
        int g = gr[i];
        int pos = base[g] + run[g]++;
        g_perm[pos] = t * per + i;
    }
}

// ------------- TF32 GEMM: cp.async 3-stage + ldmatrix, 2 CTAs/SM ------------
// Expert launches use grid (ncol=8, tile=48): bid = ncol + tile*8, so the
// sorted-full-first tile list puts only partial/empty tiles in wave 2.
constexpr int BM = 128, BN = 128, BK = 32, TPB = 256;
constexpr int A_SW = 36;
constexpr int A_STG = BM * A_SW;             // 4608
constexpr int SB = 136;
constexpr int B_STG = BK * SB;               // 4352
constexpr int B0W = 3 * A_STG;               // 13824
constexpr int BIAS_W = B0W + 3 * B_STG;      // 26880
constexpr int SMEM_WORDS = BIAS_W + BN;      // 27008
constexpr int SMEM_BYTES = SMEM_WORDS * 4;   // 108032

__device__ __forceinline__ void cp16(uint32_t dst, const float* src) {
    asm volatile("cp.async.cg.shared.global [%0], [%1], 16;"
                 :: "r"(dst), "l"(src) : "memory");
}

template<bool EXPERT, bool GATHER_A, bool SCATTER_C, bool GELU>
__global__ void __launch_bounds__(TPB, 2)
gemm_tf32(const float* __restrict__ A, const float* __restrict__ Bw,
          const float* __restrict__ bias, float* __restrict__ C,
          int N, int K,
          const int* __restrict__ perm,
          const int* __restrict__ tgen, const int* __restrict__ tstart,
          const int* __restrict__ trows, const int* __restrict__ tcnt)
{
    extern __shared__ float sm[];

    int m0, rows, genre = 0, n0;
    if (EXPERT) {
        int tile = blockIdx.y;
        if (tile >= *tcnt) return;
        genre = tgen[tile];
        m0    = tstart[tile];
        rows  = trows[tile];
        n0    = blockIdx.x * BN;
    } else {
        m0 = blockIdx.x * BM;
        rows = BM;
        n0 = blockIdx.y * BN;
    }
    const float* Bsel = EXPERT ? Bw + (size_t)genre * K * N : Bw;
    const float* bsel = EXPERT ? bias + genre * N : bias;

    const int tid = threadIdx.x;
    if (tid < BN) sm[BIAS_W + tid] = bsel[n0 + tid];

    uint32_t smb;
    asm("{ .reg .u64 t; cvta.to.shared.u64 t, %1; cvt.u32.u64 %0, t; }"
        : "=r"(smb) : "l"(sm));

    // ---- A cp.async mapping ----
    const int row0 = tid >> 3;
    const int seg  = tid & 7;
    const float* aG[4];
    uint32_t awD[4];
#pragma unroll
    for (int i = 0; i < 4; i++) {
        int r = row0 + 32 * i;
        int lrc = r < rows ? r : (rows - 1);
        int src = m0 + lrc;
        if (GATHER_A) src = perm[src];
        aG[i]  = A + (size_t)src * K + seg * 4;
        awD[i] = (uint32_t)(r * A_SW + seg * 4) * 4;
    }
    // ---- B cp.async mapping ----
    const float* bG[4];
    uint32_t bwD[4];
#pragma unroll
    for (int j = 0; j < 4; j++) {
        int v = tid + TPB * j;
        int kB = v >> 5, n4 = v & 31;
        bG[j]  = Bsel + (size_t)kB * N + n0 + n4 * 4;
        bwD[j] = (uint32_t)(kB * SB + n4 * 4) * 4;
    }

    const int nk = K / BK;

    auto issue = [&](int kt) {
        const uint32_t as = smb + (uint32_t)((kt % 3) * A_STG) * 4;
        const uint32_t bs = smb + (uint32_t)(B0W + (kt % 3) * B_STG) * 4;
        const int ko = kt * BK;
#pragma unroll
        for (int i = 0; i < 4; i++) cp16(as + awD[i], aG[i] + ko);
#pragma unroll
        for (int j = 0; j < 4; j++) cp16(bs + bwD[j], bG[j] + (size_t)ko * N);
        asm volatile("cp.async.commit_group;" ::: "memory");
    };

    issue(0);
    issue(1);
    asm volatile("cp.async.wait_group 1;" ::: "memory");
    __syncthreads();

    // ---- compute mapping: 8 warps, warp tile 64x32 ----
    const int wid = tid >> 5, lane = tid & 31;
    const int wm = (wid >> 2) * 64;
    const int wn = (wid & 3) * 32;
    const int grp = lane >> 2, qid = lane & 3;
    const int mtBase = wm >> 4;
    const uint32_t lmOff = (uint32_t)(((lane & 15) * A_SW + (lane >> 4) * 4) * 4);

    bool mAct[4];
#pragma unroll
    for (int mt = 0; mt < 4; mt++) mAct[mt] = (wm + mt * 16) < rows;

    float acc[4][4][4];
#pragma unroll
    for (int i = 0; i < 4; i++)
#pragma unroll
        for (int j = 0; j < 4; j++)
#pragma unroll
            for (int q = 0; q < 4; q++) acc[i][j][q] = 0.f;

    for (int kt = 0; kt < nk; kt++) {
        if (kt + 2 < nk) issue(kt + 2);

        const uint32_t asB = smb + (uint32_t)((kt % 3) * A_STG) * 4;
        const int bsW = B0W + (kt % 3) * B_STG;
#pragma unroll
        for (int ks = 0; ks < 4; ks++) {
            uint32_t a[4][4];
#pragma unroll
            for (int mt = 0; mt < 4; mt++) {
                if (mAct[mt]) {
                    uint32_t ad = asB + lmOff + (uint32_t)((mtBase + mt) * 16 * A_SW * 4 + ks * 32);
                    asm volatile(
                        "ldmatrix.sync.aligned.m8n8.x4.shared.b16 {%0,%1,%2,%3}, [%4];"
                        : "=r"(a[mt][0]), "=r"(a[mt][1]), "=r"(a[mt][2]), "=r"(a[mt][3])
                        : "r"(ad));
                }
            }
            unsigned bfr[4][2];
#pragma unroll
            for (int nt = 0; nt < 4; nt++) {
                int col = wn + nt * 8 + grp;
                bfr[nt][0] = __float_as_uint(sm[bsW + (ks * 8 + qid) * SB + col]);
                bfr[nt][1] = __float_as_uint(sm[bsW + (ks * 8 + qid + 4) * SB + col]);
            }
#pragma unroll
            for (int mt = 0; mt < 4; mt++) {
                if (!mAct[mt]) continue;
#pragma unroll
                for (int nt = 0; nt < 4; nt++) {
                    float* d = acc[mt][nt];
                    asm volatile(
                        "mma.sync.aligned.m16n8k8.row.col.f32.tf32.tf32.f32 "
                        "{%0,%1,%2,%3},{%4,%5,%6,%7},{%8,%9},{%0,%1,%2,%3};\n"
                        : "+f"(d[0]), "+f"(d[1]), "+f"(d[2]), "+f"(d[3])
                        : "r"(a[mt][0]), "r"(a[mt][1]), "r"(a[mt][2]), "r"(a[mt][3]),
                          "r"(bfr[nt][0]), "r"(bfr[nt][1]));
                }
            }
        }
        if (kt + 1 < nk) {
            if (kt + 2 < nk) {
                asm volatile("cp.async.wait_group 1;" ::: "memory");
            } else {
                asm volatile("cp.async.wait_group 0;" ::: "memory");
            }
        }
        __syncthreads();
    }

    // ---- epilogue ----
#pragma unroll
    for (int mt = 0; mt < 4; mt++) {
#pragma unroll
        for (int h = 0; h < 2; h++) {
            int rl = wm + mt * 16 + grp + 8 * h;
            if (rl < rows) {
                int orow = m0 + rl;
                if (SCATTER_C) orow = perm[orow];
                float* crow = C + (size_t)orow * N + n0 + wn;
#pragma unroll
                for (int nt = 0; nt < 4; nt++) {
                    int c = nt * 8 + 2 * qid;
                    float x0 = acc[mt][nt][2 * h + 0] + sm[BIAS_W + wn + c];
                    float x1 = acc[mt][nt][2 * h + 1] + sm[BIAS_W + wn + c + 1];
                    if (GELU) {
                        x0 = tfr(gelu_f(x0));
                        x1 = tfr(gelu_f(x1));
                    }
                    *(float2*)(crow + c) = make_float2(x0, x1);
                }
            }
        }
    }
}

// ---------------- launcher ----------------
extern "C" void kernel_launch(void* const* d_in, const int* in_sizes, int n_in,
                              void* d_out, int out_size) {
    const int*   genre = (const int*)  d_in[1];
    const float* z     = (const float*)d_in[2];
    const float* mu    = (const float*)d_in[3];
    const float* sigma = (const float*)d_in[4];
    const float* Ws1   = (const float*)d_in[5];
    const float* bs1   = (const float*)d_in[6];
    const float* Ws2   = (const float*)d_in[7];
    const float* bs2   = (const float*)d_in[8];
    const float* We1   = (const float*)d_in[9];
    const float* be1   = (const float*)d_in[10];
    const float* We2   = (const float*)d_in[11];
    const float* be2   = (const float*)d_in[12];
    float* out = (float*)d_out;

    void *px, *ps1, *ps2, *pw1, *pw2, *pe1, *pe2, *pperm, *ptg, *pts, *ptr_, *ptc;
    cudaGetSymbolAddress(&px,   g_x);
    cudaGetSymbolAddress(&ps1,  g_s1);
    cudaGetSymbolAddress(&ps2,  g_s2);
    cudaGetSymbolAddress(&pw1,  g_ws1);
    cudaGetSymbolAddress(&pw2,  g_ws2);
    cudaGetSymbolAddress(&pe1,  g_we1);
    cudaGetSymbolAddress(&pe2,  g_we2);
    cudaGetSymbolAddress(&pperm, g_perm);
    cudaGetSymbolAddress(&ptg,  g_tile_genre);
    cudaGetSymbolAddress(&pts,  g_tile_start);
    cudaGetSymbolAddress(&ptr_, g_tile_rows);
    cudaGetSymbolAddress(&ptc,  g_tile_count);
    float* x   = (float*)px;
    float* s1  = (float*)ps1;
    float* s2  = (float*)ps2;
    float* ws1 = (float*)pw1;
    float* ws2 = (float*)pw2;
    float* we1 = (float*)pe1;
    float* we2 = (float*)pe2;
    const int* perm = (const int*)pperm;
    const int* tg = (const int*)ptg;
    const int* ts = (const int*)pts;
    const int* tr = (const int*)ptr_;
    const int* tc = (const int*)ptc;

    cudaFuncSetAttribute(gemm_tf32<false,false,false,true>,
                         cudaFuncAttributeMaxDynamicSharedMemorySize, SMEM_BYTES);
    cudaFuncSetAttribute(gemm_tf32<true,true,false,true>,
                         cudaFuncAttributeMaxDynamicSharedMemorySize, SMEM_BYTES);
    cudaFuncSetAttribute(gemm_tf32<true,false,true,false>,
                         cudaFuncAttributeMaxDynamicSharedMemorySize, SMEM_BYTES);

    // 0) pre-round weights to tf32 (4 float4 per thread)
    {
        int n1 = INDIM * DIM / 4, n2 = DIM * DIM / 4, n3 = NGEN * DIM * DIM / 4;
        round_w<<<(n1 / 4 + 255) / 256, 256>>>((const float4*)Ws1, (float4*)ws1, n1);
        round_w<<<(n2 / 4 + 255) / 256, 256>>>((const float4*)Ws2, (float4*)ws2, n2);
        round_w<<<(n3 / 4 + 255) / 256, 256>>>((const float4*)We1, (float4*)we1, n3);
        round_w<<<(n3 / 4 + 255) / 256, 256>>>((const float4*)We2, (float4*)we2, n3);
    }

    // 1) reparameterized sample (tf32-rounded)
    {
        int total = BSZ * INDIM / 4;
        noise_kernel<<<(total + 255) / 256, 256>>>(
            (const float4*)mu, (const float4*)sigma, (const float4*)z, genre, (float4*)x);
    }
    // 2) grouping (full tiles first)
    group_kernel<<<1, 256>>>(genre);

    // 3) shared MLP
    dim3 gs(BSZ / BM, DIM / BN);
    gemm_tf32<false,false,false,true><<<gs, TPB, SMEM_BYTES>>>(
        x, ws1, bs1, s1, DIM, INDIM, nullptr, nullptr, nullptr, nullptr, nullptr);
    gemm_tf32<false,false,false,true><<<gs, TPB, SMEM_BYTES>>>(
        s1, ws2, bs2, s2, DIM, DIM, nullptr, nullptr, nullptr, nullptr, nullptr);

    // 4) expert layers: grid (ncol, tile) so wave 2 holds only partial tiles
    dim3 ge(DIM / BN, MAX_TILES);
    gemm_tf32<true,true,false,true><<<ge, TPB, SMEM_BYTES>>>(
        s2, we1, be1, s1, DIM, DIM, perm, tg, ts, tr, tc);
    gemm_tf32<true,false,true,false><<<ge, TPB, SMEM_BYTES>>>(
        s1, we2, be2, out, DIM, DIM, perm, tg, ts, tr, tc);
}

// round 12
// speedup vs baseline: 1.0400x; 1.0400x over previous
#include <cuda_runtime.h>
#include <cstdint>
#include <math.h>

// ---------------- problem constants ----------------
#define NGEN 10
#define BSZ  4096
#define INDIM 512
#define DIM  1024
#define MAX_TILES 48

// ---------------- scratch ----------------
__device__ float g_x [BSZ * INDIM];
__device__ float g_s1[BSZ * DIM];
__device__ float g_s2[BSZ * DIM];
__device__ float g_ws1[INDIM * DIM];
__device__ float g_ws2[DIM * DIM];
__device__ float g_we1[NGEN * DIM * DIM];
__device__ float g_we2[NGEN * DIM * DIM];
__device__ int   g_perm[BSZ];
__device__ int   g_tile_genre[MAX_TILES];
__device__ int   g_tile_start[MAX_TILES];
__device__ int   g_tile_rows [MAX_TILES];
__device__ int   g_tile_count;

// ---------------- helpers ----------------
__device__ __forceinline__ unsigned f2tf(float x) {
    unsigned r;
    asm("cvt.rna.tf32.f32 %0, %1;" : "=r"(r) : "f"(x));
    return r;
}
__device__ __forceinline__ float tfr(float x) {
    return __uint_as_float(f2tf(x));
}
__device__ __forceinline__ float gelu_f(float x) {
    return 0.5f * x * (1.0f + erff(x * 0.70710678118654752f));
}

// ---------------- tf32 pre-rounding of weights (1 float4 / thread) ---------
__global__ void round_w(const float4* __restrict__ s, float4* __restrict__ d, int n4) {
    int i = blockIdx.x * blockDim.x + threadIdx.x;
    if (i < n4) {
        float4 v = s[i];
        d[i] = make_float4(tfr(v.x), tfr(v.y), tfr(v.z), tfr(v.w));
    }
}

// ---------------- reparameterized sample (tf32-rounded output) -------------
__global__ void noise_kernel(const float4* __restrict__ mu,
                             const float4* __restrict__ sig,
                             const float4* __restrict__ z,
                             const int* __restrict__ genre,
                             float4* __restrict__ x) {
    const int C4 = INDIM / 4;
    int i = blockIdx.x * blockDim.x + threadIdx.x;
    if (i >= BSZ * C4) return;
    int row = i / C4, c = i - row * C4;
    int g = genre[row];
    float4 m = mu[g * C4 + c];
    float4 s = sig[g * C4 + c];
    float4 zz = z[i];
    float4 o;
    o.x = tfr(m.x + (fabsf(s.x) + 1e-8f) * zz.x);
    o.y = tfr(m.y + (fabsf(s.y) + 1e-8f) * zz.y);
    o.z = tfr(m.z + (fabsf(s.z) + 1e-8f) * zz.z);
    o.w = tfr(m.w + (fabsf(s.w) + 1e-8f) * zz.w);
    x[i] = o;
}

// ---------------- grouping (full tiles first, partial last) ----------------
__global__ void group_kernel(const int* __restrict__ genre) {
    __shared__ int cnt[256 * NGEN];
    __shared__ int tot[NGEN];
    __shared__ int base[NGEN];
    int t = threadIdx.x;
    const int per = BSZ / 256;

    int lc[NGEN];
#pragma unroll
    for (int g = 0; g < NGEN; g++) lc[g] = 0;
    int gr[per];
    for (int i = 0; i < per; i++) {
        int g = genre[t * per + i];
        gr[i] = g;
        lc[g]++;
    }
    for (int g = 0; g < NGEN; g++) cnt[t * NGEN + g] = lc[g];
    __syncthreads();

    if (t < NGEN) {
        int s = 0;
        for (int tt = 0; tt < 256; tt++) {
            int v = cnt[tt * NGEN + t];
            cnt[tt * NGEN + t] = s;
            s += v;
        }
        tot[t] = s;
    }
    __syncthreads();

    if (t == 0) {
        int off = 0;
        for (int g = 0; g < NGEN; g++) { base[g] = off; off += tot[g]; }
        int T = 0;
        int prows[NGEN], pstart[NGEN];
        for (int g = 0; g < NGEN; g++) {
            int c = tot[g], s0 = base[g];
            while (c >= 128) {
                g_tile_genre[T] = g;
                g_tile_start[T] = s0;
                g_tile_rows[T]  = 128;
                s0 += 128; c -= 128; T++;
            }
            prows[g] = c; pstart[g] = s0;
        }
        for (int g = 0; g < NGEN; g++) {
            if (prows[g] > 0) {
                g_tile_genre[T] = g;
                g_tile_start[T] = pstart[g];
                g_tile_rows[T]  = prows[g];
                T++;
            }
        }
        g_tile_count = T;
    }
    __syncthreads();

    int run[NGEN];
#pragma unroll
    for (int g = 0; g < NGEN; g++) run[g] = cnt[t * NGEN + g];
    for (int i = 0; i < per; i++) {
        int g = gr[i];
        int pos = base[g] + run[g]++;
        g_perm[pos] = t * per + i;
    }
}

// --- TF32 GEMM: 128 threads, 4 warps of 64x64, cp.async 3-stage, 2 CTA/SM ---
constexpr int BM = 128, BN = 128, BK = 32, TPB = 128;
constexpr int A_SW = 36;
constexpr int A_STG = BM * A_SW;             // 4608
constexpr int SB = 136;
constexpr int B_STG = BK * SB;               // 4352
constexpr int B0W = 3 * A_STG;               // 13824
constexpr int BIAS_W = B0W + 3 * B_STG;      // 26880
constexpr int SMEM_WORDS = BIAS_W + BN;      // 27008
constexpr int SMEM_BYTES = SMEM_WORDS * 4;   // 108032

__device__ __forceinline__ void cp16(uint32_t dst, const float* src) {
    asm volatile("cp.async.cg.shared.global [%0], [%1], 16;"
                 :: "r"(dst), "l"(src) : "memory");
}

template<bool EXPERT, bool GATHER_A, bool SCATTER_C, bool GELU>
__global__ void __launch_bounds__(TPB, 2)
gemm_tf32(const float* __restrict__ A, const float* __restrict__ Bw,
          const float* __restrict__ bias, float* __restrict__ C,
          int N, int K,
          const int* __restrict__ perm,
          const int* __restrict__ tgen, const int* __restrict__ tstart,
          const int* __restrict__ trows, const int* __restrict__ tcnt)
{
    extern __shared__ float sm[];

    int m0, rows, genre = 0, n0;
    if (EXPERT) {
        int tile = blockIdx.x;
        if (tile >= *tcnt) return;
        genre = tgen[tile];
        m0    = tstart[tile];
        rows  = trows[tile];
        n0    = blockIdx.y * BN;
    } else {
        m0 = blockIdx.x * BM;
        rows = BM;
        n0 = blockIdx.y * BN;
    }
    const float* Bsel = EXPERT ? Bw + (size_t)genre * K * N : Bw;
    const float* bsel = EXPERT ? bias + genre * N : bias;

    const int tid = threadIdx.x;
    sm[BIAS_W + tid] = bsel[n0 + tid];   // 128 threads stage 128 biases

    uint32_t smb;
    asm("{ .reg .u64 t; cvta.to.shared.u64 t, %1; cvt.u32.u64 %0, t; }"
        : "=r"(smb) : "l"(sm));

    // ---- A cp.async mapping: 8 chunks/thread (rows rowb+16i, fixed seg) ----
    const int rowb = tid >> 3;
    const int seg  = tid & 7;
    const float* aG[8];
    uint32_t awD[8];
#pragma unroll
    for (int i = 0; i < 8; i++) {
        int r = rowb + 16 * i;
        int lrc = r < rows ? r : (rows - 1);
        int src = m0 + lrc;
        if (GATHER_A) src = perm[src];
        aG[i]  = A + (size_t)src * K + seg * 4;
        awD[i] = (uint32_t)(r * A_SW + seg * 4) * 4;
    }
    // ---- B cp.async mapping: 8 chunks/thread (rows kb+4j, fixed n4) ----
    const int kb = tid >> 5;
    const int n4 = tid & 31;
    const float* bG[8];
    uint32_t bwD[8];
#pragma unroll
    for (int j = 0; j < 8; j++) {
        int k = kb + 4 * j;
        bG[j]  = Bsel + (size_t)k * N + n0 + n4 * 4;
        bwD[j] = (uint32_t)(k * SB + n4 * 4) * 4;
    }

    const int nk = K / BK;

    auto issue = [&](int kt) {
        const uint32_t as = smb + (uint32_t)((kt % 3) * A_STG) * 4;
        const uint32_t bs = smb + (uint32_t)(B0W + (kt % 3) * B_STG) * 4;
        const int ko = kt * BK;
#pragma unroll
        for (int i = 0; i < 8; i++) cp16(as + awD[i], aG[i] + ko);
#pragma unroll
        for (int j = 0; j < 8; j++) cp16(bs + bwD[j], bG[j] + (size_t)ko * N);
        asm volatile("cp.async.commit_group;" ::: "memory");
    };

    issue(0);
    issue(1);
    asm volatile("cp.async.wait_group 1;" ::: "memory");
    __syncthreads();

    // ---- compute mapping: 4 warps, warp tile 64x64 ----
    const int wid = tid >> 5, lane = tid & 31;
    const int wm = (wid >> 1) * 64;          // 0 / 64
    const int wn = (wid & 1) * 64;           // 0 / 64
    const int grp = lane >> 2, qid = lane & 3;
    const int mtBase = wm >> 4;              // 0 or 4
    const uint32_t lmOff = (uint32_t)(((lane & 15) * A_SW + (lane >> 4) * 4) * 4);

    bool mAct[4];
#pragma unroll
    for (int mt = 0; mt < 4; mt++) mAct[mt] = (wm + mt * 16) < rows;

    float acc[4][8][4];
#pragma unroll
    for (int i = 0; i < 4; i++)
#pragma unroll
        for (int j = 0; j < 8; j++)
#pragma unroll
            for (int q = 0; q < 4; q++) acc[i][j][q] = 0.f;

    for (int kt = 0; kt < nk; kt++) {
        if (kt + 2 < nk) issue(kt + 2);

        const uint32_t asB = smb + (uint32_t)((kt % 3) * A_STG) * 4;
        const int bsW = B0W + (kt % 3) * B_STG;

        // fragment double-buffer over ks
        uint32_t af[2][4][4];
        unsigned bf[2][8][2];

        // load ks=0 into buf 0
#pragma unroll
        for (int mt = 0; mt < 4; mt++) {
            if (mAct[mt]) {
                uint32_t ad = asB + lmOff + (uint32_t)((mtBase + mt) * 16 * A_SW * 4);
                asm volatile(
                    "ldmatrix.sync.aligned.m8n8.x4.shared.b16 {%0,%1,%2,%3}, [%4];"
                    : "=r"(af[0][mt][0]), "=r"(af[0][mt][1]),
                      "=r"(af[0][mt][2]), "=r"(af[0][mt][3])
                    : "r"(ad));
            }
        }
#pragma unroll
        for (int nt = 0; nt < 8; nt++) {
            int col = wn + nt * 8 + grp;
            bf[0][nt][0] = __float_as_uint(sm[bsW + qid * SB + col]);
            bf[0][nt][1] = __float_as_uint(sm[bsW + (qid + 4) * SB + col]);
        }

#pragma unroll
        for (int ks = 0; ks < 4; ks++) {
            const int cur = ks & 1, nxt = cur ^ 1;
            if (ks < 3) {
#pragma unroll
                for (int mt = 0; mt < 4; mt++) {
                    if (mAct[mt]) {
                        uint32_t ad = asB + lmOff
                                    + (uint32_t)((mtBase + mt) * 16 * A_SW * 4 + (ks + 1) * 32);
                        asm volatile(
                            "ldmatrix.sync.aligned.m8n8.x4.shared.b16 {%0,%1,%2,%3}, [%4];"
                            : "=r"(af[nxt][mt][0]), "=r"(af[nxt][mt][1]),
                              "=r"(af[nxt][mt][2]), "=r"(af[nxt][mt][3])
                            : "r"(ad));
                    }
                }
#pragma unroll
                for (int nt = 0; nt < 8; nt++) {
                    int col = wn + nt * 8 + grp;
                    bf[nxt][nt][0] = __float_as_uint(sm[bsW + ((ks + 1) * 8 + qid) * SB + col]);
                    bf[nxt][nt][1] = __float_as_uint(sm[bsW + ((ks + 1) * 8 + qid + 4) * SB + col]);
                }
            }
#pragma unroll
            for (int mt = 0; mt < 4; mt++) {
                if (!mAct[mt]) continue;
#pragma unroll
                for (int nt = 0; nt < 8; nt++) {
                    float* d = acc[mt][nt];
                    asm volatile(
                        "mma.sync.aligned.m16n8k8.row.col.f32.tf32.tf32.f32 "
                        "{%0,%1,%2,%3},{%4,%5,%6,%7},{%8,%9},{%0,%1,%2,%3};\n"
                        : "+f"(d[0]), "+f"(d[1]), "+f"(d[2]), "+f"(d[3])
                        : "r"(af[cur][mt][0]), "r"(af[cur][mt][1]),
                          "r"(af[cur][mt][2]), "r"(af[cur][mt][3]),
                          "r"(bf[cur][nt][0]), "r"(bf[cur][nt][1]));
                }
            }
        }
        if (kt + 1 < nk) {
            if (kt + 2 < nk) {
                asm volatile("cp.async.wait_group 1;" ::: "memory");
            } else {
                asm volatile("cp.async.wait_group 0;" ::: "memory");
            }
        }
        __syncthreads();
    }

    // ---- epilogue ----
#pragma unroll
    for (int mt = 0; mt < 4; mt++) {
#pragma unroll
        for (int h = 0; h < 2; h++) {
            int rl = wm + mt * 16 + grp + 8 * h;
            if (rl < rows) {
                int orow = m0 + rl;
                if (SCATTER_C) orow = perm[orow];
                float* crow = C + (size_t)orow * N + n0 + wn;
#pragma unroll
                for (int nt = 0; nt < 8; nt++) {
                    int c = nt * 8 + 2 * qid;
                    float x0 = acc[mt][nt][2 * h + 0] + sm[BIAS_W + wn + c];
                    float x1 = acc[mt][nt][2 * h + 1] + sm[BIAS_W + wn + c + 1];
                    if (GELU) {
                        x0 = tfr(gelu_f(x0));
                        x1 = tfr(gelu_f(x1));
                    }
                    *(float2*)(crow + c) = make_float2(x0, x1);
                }
            }
        }
    }
}

// ---------------- launcher ----------------
extern "C" void kernel_launch(void* const* d_in, const int* in_sizes, int n_in,
                              void* d_out, int out_size) {
    const int*   genre = (const int*)  d_in[1];
    const float* z     = (const float*)d_in[2];
    const float* mu    = (const float*)d_in[3];
    const float* sigma = (const float*)d_in[4];
    const float* Ws1   = (const float*)d_in[5];
    const float* bs1   = (const float*)d_in[6];
    const float* Ws2   = (const float*)d_in[7];
    const float* bs2   = (const float*)d_in[8];
    const float* We1   = (const float*)d_in[9];
    const float* be1   = (const float*)d_in[10];
    const float* We2   = (const float*)d_in[11];
    const float* be2   = (const float*)d_in[12];
    float* out = (float*)d_out;

    void *px, *ps1, *ps2, *pw1, *pw2, *pe1, *pe2, *pperm, *ptg, *pts, *ptr_, *ptc;
    cudaGetSymbolAddress(&px,   g_x);
    cudaGetSymbolAddress(&ps1,  g_s1);
    cudaGetSymbolAddress(&ps2,  g_s2);
    cudaGetSymbolAddress(&pw1,  g_ws1);
    cudaGetSymbolAddress(&pw2,  g_ws2);
    cudaGetSymbolAddress(&pe1,  g_we1);
    cudaGetSymbolAddress(&pe2,  g_we2);
    cudaGetSymbolAddress(&pperm, g_perm);
    cudaGetSymbolAddress(&ptg,  g_tile_genre);
    cudaGetSymbolAddress(&pts,  g_tile_start);
    cudaGetSymbolAddress(&ptr_, g_tile_rows);
    cudaGetSymbolAddress(&ptc,  g_tile_count);
    float* x   = (float*)px;
    float* s1  = (float*)ps1;
    float* s2  = (float*)ps2;
    float* ws1 = (float*)pw1;
    float* ws2 = (float*)pw2;
    float* we1 = (float*)pe1;
    float* we2 = (float*)pe2;
    const int* perm = (const int*)pperm;
    const int* tg = (const int*)ptg;
    const int* ts = (const int*)pts;
    const int* tr = (const int*)ptr_;
    const int* tc = (const int*)ptc;

    cudaFuncSetAttribute(gemm_tf32<false,false,false,true>,
                         cudaFuncAttributeMaxDynamicSharedMemorySize, SMEM_BYTES);
    cudaFuncSetAttribute(gemm_tf32<true,true,false,true>,
                         cudaFuncAttributeMaxDynamicSharedMemorySize, SMEM_BYTES);
    cudaFuncSetAttribute(gemm_tf32<true,false,true,false>,
                         cudaFuncAttributeMaxDynamicSharedMemorySize, SMEM_BYTES);

    // 0) pre-round weights to tf32 (1 float4 per thread — measured best)
    round_w<<<(INDIM * DIM / 4 + 255) / 256, 256>>>((const float4*)Ws1, (float4*)ws1, INDIM * DIM / 4);
    round_w<<<(DIM * DIM / 4 + 255) / 256, 256>>>((const float4*)Ws2, (float4*)ws2, DIM * DIM / 4);
    round_w<<<(NGEN * DIM * DIM / 4 + 255) / 256, 256>>>((const float4*)We1, (float4*)we1, NGEN * DIM * DIM / 4);
    round_w<<<(NGEN * DIM * DIM / 4 + 255) / 256, 256>>>((const float4*)We2, (float4*)we2, NGEN * DIM * DIM / 4);

    // 1) reparameterized sample (tf32-rounded)
    {
        int total = BSZ * INDIM / 4;
        noise_kernel<<<(total + 255) / 256, 256>>>(
            (const float4*)mu, (const float4*)sigma, (const float4*)z, genre, (float4*)x);
    }
    // 2) grouping (full tiles first)
    group_kernel<<<1, 256>>>(genre);

    // 3) shared MLP
    dim3 gs(BSZ / BM, DIM / BN);
    gemm_tf32<false,false,false,true><<<gs, TPB, SMEM_BYTES>>>(
        x, ws1, bs1, s1, DIM, INDIM, nullptr, nullptr, nullptr, nullptr, nullptr);
    gemm_tf32<false,false,false,true><<<gs, TPB, SMEM_BYTES>>>(
        s1, ws2, bs2, s2, DIM, DIM, nullptr, nullptr, nullptr, nullptr, nullptr);

    // 4) expert layers
    dim3 ge(MAX_TILES, DIM / BN);
    gemm_tf32<true,true,false,true><<<ge, TPB, SMEM_BYTES>>>(
        s2, we1, be1, s1, DIM, DIM, perm, tg, ts, tr, tc);
    gemm_tf32<true,false,true,false><<<ge, TPB, SMEM_BYTES>>>(
        s1, we2, be2, out, DIM, DIM, perm, tg, ts, tr, tc);
}

// round 13
// speedup vs baseline: 1.0694x; 1.0283x over previous
#include <cuda_runtime.h>
#include <cstdint>
#include <math.h>

// ---------------- problem constants ----------------
#define NGEN 10
#define BSZ  4096
#define INDIM 512
#define DIM  1024
#define MAX_TILES 48

// ---------------- scratch ----------------
__device__ float g_x [BSZ * INDIM];
__device__ float g_s1[BSZ * DIM];
__device__ float g_s2[BSZ * DIM];
__device__ float g_ws1[INDIM * DIM];
__device__ float g_ws2[DIM * DIM];
__device__ float g_we1[NGEN * DIM * DIM];
__device__ float g_we2[NGEN * DIM * DIM];
__device__ int   g_perm[BSZ];
__device__ int   g_tile_genre[MAX_TILES];
__device__ int   g_tile_start[MAX_TILES];
__device__ int   g_tile_rows [MAX_TILES];
__device__ int   g_tile_count;

// ---------------- helpers ----------------
__device__ __forceinline__ unsigned f2tf(float x) {
    unsigned r;
    asm("cvt.rna.tf32.f32 %0, %1;" : "=r"(r) : "f"(x));
    return r;
}
__device__ __forceinline__ float tfr(float x) {
    return __uint_as_float(f2tf(x));
}
__device__ __forceinline__ float gelu_f(float x) {
    return 0.5f * x * (1.0f + erff(x * 0.70710678118654752f));
}

// ---------------- tf32 pre-rounding ----------------
__global__ void round_w(const float4* __restrict__ s, float4* __restrict__ d, int n4) {
    int i = blockIdx.x * blockDim.x + threadIdx.x;
    if (i < n4) {
        float4 v = s[i];
        d[i] = make_float4(tfr(v.x), tfr(v.y), tfr(v.z), tfr(v.w));
    }
}

// fused rounding of Ws2 + We1 + We2 (side stream)
__global__ void round_all(const float4* __restrict__ s2w, float4* __restrict__ d2w, int n2,
                          const float4* __restrict__ e1s, float4* __restrict__ e1d,
                          const float4* __restrict__ e2s, float4* __restrict__ e2d, int n3) {
    int i = blockIdx.x * blockDim.x + threadIdx.x;
    const float4* s;
    float4* d;
    int j;
    if (i < n2)            { s = s2w; d = d2w; j = i; }
    else if (i < n2 + n3)  { s = e1s; d = e1d; j = i - n2; }
    else if (i < n2 + 2*n3){ s = e2s; d = e2d; j = i - n2 - n3; }
    else return;
    float4 v = s[j];
    d[j] = make_float4(tfr(v.x), tfr(v.y), tfr(v.z), tfr(v.w));
}

// ---------------- reparameterized sample (tf32-rounded output) -------------
__global__ void noise_kernel(const float4* __restrict__ mu,
                             const float4* __restrict__ sig,
                             const float4* __restrict__ z,
                             const int* __restrict__ genre,
                             float4* __restrict__ x) {
    const int C4 = INDIM / 4;
    int i = blockIdx.x * blockDim.x + threadIdx.x;
    if (i >= BSZ * C4) return;
    int row = i / C4, c = i - row * C4;
    int g = genre[row];
    float4 m = mu[g * C4 + c];
    float4 s = sig[g * C4 + c];
    float4 zz = z[i];
    float4 o;
    o.x = tfr(m.x + (fabsf(s.x) + 1e-8f) * zz.x);
    o.y = tfr(m.y + (fabsf(s.y) + 1e-8f) * zz.y);
    o.z = tfr(m.z + (fabsf(s.z) + 1e-8f) * zz.z);
    o.w = tfr(m.w + (fabsf(s.w) + 1e-8f) * zz.w);
    x[i] = o;
}

// ---------------- grouping (full tiles first, partial last) ----------------
__global__ void group_kernel(const int* __restrict__ genre) {
    __shared__ int cnt[256 * NGEN];
    __shared__ int tot[NGEN];
    __shared__ int base[NGEN];
    int t = threadIdx.x;
    const int per = BSZ / 256;

    int lc[NGEN];
#pragma unroll
    for (int g = 0; g < NGEN; g++) lc[g] = 0;
    int gr[per];
    for (int i = 0; i < per; i++) {
        int g = genre[t * per + i];
        gr[i] = g;
        lc[g]++;
    }
    for (int g = 0; g < NGEN; g++) cnt[t * NGEN + g] = lc[g];
    __syncthreads();

    if (t < NGEN) {
        int s = 0;
        for (int tt = 0; tt < 256; tt++) {
            int v = cnt[tt * NGEN + t];
            cnt[tt * NGEN + t] = s;
            s += v;
        }
        tot[t] = s;
    }
    __syncthreads();

    if (t == 0) {
        int off = 0;
        for (int g = 0; g < NGEN; g++) { base[g] = off; off += tot[g]; }
        int T = 0;
        int prows[NGEN], pstart[NGEN];
        for (int g = 0; g < NGEN; g++) {
            int c = tot[g], s0 = base[g];
            while (c >= 128) {
                g_tile_genre[T] = g;
                g_tile_start[T] = s0;
                g_tile_rows[T]  = 128;
                s0 += 128; c -= 128; T++;
            }
            prows[g] = c; pstart[g] = s0;
        }
        for (int g = 0; g < NGEN; g++) {
            if (prows[g] > 0) {
                g_tile_genre[T] = g;
                g_tile_start[T] = pstart[g];
                g_tile_rows[T]  = prows[g];
                T++;
            }
        }
        g_tile_count = T;
    }
    __syncthreads();

    int run[NGEN];
#pragma unroll
    for (int g = 0; g < NGEN; g++) run[g] = cnt[t * NGEN + g];
    for (int i = 0; i < per; i++) {
        int g = gr[i];
        int pos = base[g] + run[g]++;
        g_perm[pos] = t * per + i;
    }
}

// ------------- TF32 GEMM: cp.async 3-stage + ldmatrix, 2 CTAs/SM ------------
constexpr int BM = 128, BN = 128, BK = 32, TPB = 256;
constexpr int A_SW = 36;
constexpr int A_STG = BM * A_SW;             // 4608
constexpr int SB = 136;
constexpr int B_STG = BK * SB;               // 4352
constexpr int B0W = 3 * A_STG;               // 13824
constexpr int BIAS_W = B0W + 3 * B_STG;      // 26880
constexpr int SMEM_WORDS = BIAS_W + BN;      // 27008
constexpr int SMEM_BYTES = SMEM_WORDS * 4;   // 108032

__device__ __forceinline__ void cp16(uint32_t dst, const float* src) {
    asm volatile("cp.async.cg.shared.global [%0], [%1], 16;"
                 :: "r"(dst), "l"(src) : "memory");
}

template<bool EXPERT, bool GATHER_A, bool SCATTER_C, bool GELU>
__global__ void __launch_bounds__(TPB, 2)
gemm_tf32(const float* __restrict__ A, const float* __restrict__ Bw,
          const float* __restrict__ bias, float* __restrict__ C,
          int N, int K,
          const int* __restrict__ perm,
          const int* __restrict__ tgen, const int* __restrict__ tstart,
          const int* __restrict__ trows, const int* __restrict__ tcnt)
{
    extern __shared__ float sm[];

    int m0, rows, genre = 0, n0;
    if (EXPERT) {
        int tile = blockIdx.x;
        if (tile >= *tcnt) return;
        genre = tgen[tile];
        m0    = tstart[tile];
        rows  = trows[tile];
        n0    = blockIdx.y * BN;
    } else {
        m0 = blockIdx.x * BM;
        rows = BM;
        n0 = blockIdx.y * BN;
    }
    const float* Bsel = EXPERT ? Bw + (size_t)genre * K * N : Bw;
    const float* bsel = EXPERT ? bias + genre * N : bias;

    const int tid = threadIdx.x;
    if (tid < BN) sm[BIAS_W + tid] = bsel[n0 + tid];

    uint32_t smb;
    asm("{ .reg .u64 t; cvta.to.shared.u64 t, %1; cvt.u32.u64 %0, t; }"
        : "=r"(smb) : "l"(sm));

    // ---- A cp.async mapping ----
    const int row0 = tid >> 3;
    const int seg  = tid & 7;
    const float* aG[4];
    uint32_t awD[4];
#pragma unroll
    for (int i = 0; i < 4; i++) {
        int r = row0 + 32 * i;
        int lrc = r < rows ? r : (rows - 1);
        int src = m0 + lrc;
        if (GATHER_A) src = perm[src];
        aG[i]  = A + (size_t)src * K + seg * 4;
        awD[i] = (uint32_t)(r * A_SW + seg * 4) * 4;
    }
    // ---- B cp.async mapping ----
    const float* bG[4];
    uint32_t bwD[4];
#pragma unroll
    for (int j = 0; j < 4; j++) {
        int v = tid + TPB * j;
        int kB = v >> 5, n4 = v & 31;
        bG[j]  = Bsel + (size_t)kB * N + n0 + n4 * 4;
        bwD[j] = (uint32_t)(kB * SB + n4 * 4) * 4;
    }

    const int nk = K / BK;

    auto issue = [&](int kt) {
        const uint32_t as = smb + (uint32_t)((kt % 3) * A_STG) * 4;
        const uint32_t bs = smb + (uint32_t)(B0W + (kt % 3) * B_STG) * 4;
        const int ko = kt * BK;
#pragma unroll
        for (int i = 0; i < 4; i++) cp16(as + awD[i], aG[i] + ko);
#pragma unroll
        for (int j = 0; j < 4; j++) cp16(bs + bwD[j], bG[j] + (size_t)ko * N);
        asm volatile("cp.async.commit_group;" ::: "memory");
    };

    issue(0);
    issue(1);
    asm volatile("cp.async.wait_group 1;" ::: "memory");
    __syncthreads();

    // ---- compute mapping: 8 warps, warp tile 64x32 ----
    const int wid = tid >> 5, lane = tid & 31;
    const int wm = (wid >> 2) * 64;
    const int wn = (wid & 3) * 32;
    const int grp = lane >> 2, qid = lane & 3;
    const int mtBase = wm >> 4;
    const uint32_t lmOff = (uint32_t)(((lane & 15) * A_SW + (lane >> 4) * 4) * 4);

    bool mAct[4];
#pragma unroll
    for (int mt = 0; mt < 4; mt++) mAct[mt] = (wm + mt * 16) < rows;

    float acc[4][4][4];
#pragma unroll
    for (int i = 0; i < 4; i++)
#pragma unroll
        for (int j = 0; j < 4; j++)
#pragma unroll
            for (int q = 0; q < 4; q++) acc[i][j][q] = 0.f;

    for (int kt = 0; kt < nk; kt++) {
        if (kt + 2 < nk) issue(kt + 2);

        const uint32_t asB = smb + (uint32_t)((kt % 3) * A_STG) * 4;
        const int bsW = B0W + (kt % 3) * B_STG;
#pragma unroll
        for (int ks = 0; ks < 4; ks++) {
            uint32_t a[4][4];
#pragma unroll
            for (int mt = 0; mt < 4; mt++) {
                if (mAct[mt]) {
                    uint32_t ad = asB + lmOff + (uint32_t)((mtBase + mt) * 16 * A_SW * 4 + ks * 32);
                    asm volatile(
                        "ldmatrix.sync.aligned.m8n8.x4.shared.b16 {%0,%1,%2,%3}, [%4];"
                        : "=r"(a[mt][0]), "=r"(a[mt][1]), "=r"(a[mt][2]), "=r"(a[mt][3])
                        : "r"(ad));
                }
            }
            unsigned bfr[4][2];
#pragma unroll
            for (int nt = 0; nt < 4; nt++) {
                int col = wn + nt * 8 + grp;
                bfr[nt][0] = __float_as_uint(sm[bsW + (ks * 8 + qid) * SB + col]);
                bfr[nt][1] = __float_as_uint(sm[bsW + (ks * 8 + qid + 4) * SB + col]);
            }
#pragma unroll
            for (int mt = 0; mt < 4; mt++) {
                if (!mAct[mt]) continue;
#pragma unroll
                for (int nt = 0; nt < 4; nt++) {
                    float* d = acc[mt][nt];
                    asm volatile(
                        "mma.sync.aligned.m16n8k8.row.col.f32.tf32.tf32.f32 "
                        "{%0,%1,%2,%3},{%4,%5,%6,%7},{%8,%9},{%0,%1,%2,%3};\n"
                        : "+f"(d[0]), "+f"(d[1]), "+f"(d[2]), "+f"(d[3])
                        : "r"(a[mt][0]), "r"(a[mt][1]), "r"(a[mt][2]), "r"(a[mt][3]),
                          "r"(bfr[nt][0]), "r"(bfr[nt][1]));
                }
            }
        }
        if (kt + 1 < nk) {
            if (kt + 2 < nk) {
                asm volatile("cp.async.wait_group 1;" ::: "memory");
            } else {
                asm volatile("cp.async.wait_group 0;" ::: "memory");
            }
        }
        __syncthreads();
    }

    // ---- epilogue ----
#pragma unroll
    for (int mt = 0; mt < 4; mt++) {
#pragma unroll
        for (int h = 0; h < 2; h++) {
            int rl = wm + mt * 16 + grp + 8 * h;
            if (rl < rows) {
                int orow = m0 + rl;
                if (SCATTER_C) orow = perm[orow];
                float* crow = C + (size_t)orow * N + n0 + wn;
#pragma unroll
                for (int nt = 0; nt < 4; nt++) {
                    int c = nt * 8 + 2 * qid;
                    float x0 = acc[mt][nt][2 * h + 0] + sm[BIAS_W + wn + c];
                    float x1 = acc[mt][nt][2 * h + 1] + sm[BIAS_W + wn + c + 1];
                    if (GELU) {
                        x0 = tfr(gelu_f(x0));
                        x1 = tfr(gelu_f(x1));
                    }
                    *(float2*)(crow + c) = make_float2(x0, x1);
                }
            }
        }
    }
}

// ---------------- launcher ----------------
extern "C" void kernel_launch(void* const* d_in, const int* in_sizes, int n_in,
                              void* d_out, int out_size) {
    const int*   genre = (const int*)  d_in[1];
    const float* z     = (const float*)d_in[2];
    const float* mu    = (const float*)d_in[3];
    const float* sigma = (const float*)d_in[4];
    const float* Ws1   = (const float*)d_in[5];
    const float* bs1   = (const float*)d_in[6];
    const float* Ws2   = (const float*)d_in[7];
    const float* bs2   = (const float*)d_in[8];
    const float* We1   = (const float*)d_in[9];
    const float* be1   = (const float*)d_in[10];
    const float* We2   = (const float*)d_in[11];
    const float* be2   = (const float*)d_in[12];
    float* out = (float*)d_out;

    void *px, *ps1, *ps2, *pw1, *pw2, *pe1, *pe2, *pperm, *ptg, *pts, *ptr_, *ptc;
    cudaGetSymbolAddress(&px,   g_x);
    cudaGetSymbolAddress(&ps1,  g_s1);
    cudaGetSymbolAddress(&ps2,  g_s2);
    cudaGetSymbolAddress(&pw1,  g_ws1);
    cudaGetSymbolAddress(&pw2,  g_ws2);
    cudaGetSymbolAddress(&pe1,  g_we1);
    cudaGetSymbolAddress(&pe2,  g_we2);
    cudaGetSymbolAddress(&pperm, g_perm);
    cudaGetSymbolAddress(&ptg,  g_tile_genre);
    cudaGetSymbolAddress(&pts,  g_tile_start);
    cudaGetSymbolAddress(&ptr_, g_tile_rows);
    cudaGetSymbolAddress(&ptc,  g_tile_count);
    float* x   = (float*)px;
    float* s1  = (float*)ps1;
    float* s2  = (float*)ps2;
    float* ws1 = (float*)pw1;
    float* ws2 = (float*)pw2;
    float* we1 = (float*)pe1;
    float* we2 = (float*)pe2;
    const int* perm = (const int*)pperm;
    const int* tg = (const int*)ptg;
    const int* ts = (const int*)pts;
    const int* tr = (const int*)ptr_;
    const int* tc = (const int*)ptc;

    cudaFuncSetAttribute(gemm_tf32<false,false,false,true>,
                         cudaFuncAttributeMaxDynamicSharedMemorySize, SMEM_BYTES);
    cudaFuncSetAttribute(gemm_tf32<true,true,false,true>,
                         cudaFuncAttributeMaxDynamicSharedMemorySize, SMEM_BYTES);
    cudaFuncSetAttribute(gemm_tf32<true,false,true,false>,
                         cudaFuncAttributeMaxDynamicSharedMemorySize, SMEM_BYTES);

    // side stream + events (host objects only; created per call, never destroyed —
    // kernel_launch runs only for correctness + capture, replays use the graph)
    cudaStream_t s2str;
    cudaEvent_t evFork, evJoin;
    cudaStreamCreateWithFlags(&s2str, cudaStreamNonBlocking);
    cudaEventCreateWithFlags(&evFork, cudaEventDisableTiming);
    cudaEventCreateWithFlags(&evJoin, cudaEventDisableTiming);

    // 0a) critical-path round: Ws1 only (needed by L1)
    round_w<<<(INDIM * DIM / 4 + 255) / 256, 256>>>(
        (const float4*)Ws1, (float4*)ws1, INDIM * DIM / 4);

    // 0b) fork: round Ws2 + We1 + We2 on side stream (hidden under noise+group+L1)
    {
        int n2 = DIM * DIM / 4;              // 262144
        int n3 = NGEN * DIM * DIM / 4;       // 2621440
        cudaEventRecord(evFork, 0);
        cudaStreamWaitEvent(s2str, evFork, 0);
        int total = n2 + 2 * n3;
        round_all<<<(total + 255) / 256, 256, 0, s2str>>>(
            (const float4*)Ws2, (float4*)ws2, n2,
            (const float4*)We1, (float4*)we1,
            (const float4*)We2, (float4*)we2, n3);
        cudaEventRecord(evJoin, s2str);
    }

    // 1) reparameterized sample (tf32-rounded)
    {
        int total = BSZ * INDIM / 4;
        noise_kernel<<<(total + 255) / 256, 256>>>(
            (const float4*)mu, (const float4*)sigma, (const float4*)z, genre, (float4*)x);
    }
    // 2) grouping (full tiles first)
    group_kernel<<<1, 256>>>(genre);

    // 3) shared MLP layer 1 (only needs ws1)
    dim3 gs(BSZ / BM, DIM / BN);
    gemm_tf32<false,false,false,true><<<gs, TPB, SMEM_BYTES>>>(
        x, ws1, bs1, s1, DIM, INDIM, nullptr, nullptr, nullptr, nullptr, nullptr);

    // join: ws2/we1/we2 ready
    cudaStreamWaitEvent(0, evJoin, 0);

    gemm_tf32<false,false,false,true><<<gs, TPB, SMEM_BYTES>>>(
        s1, ws2, bs2, s2, DIM, DIM, nullptr, nullptr, nullptr, nullptr, nullptr);

    // 4) expert layers
    dim3 ge(MAX_TILES, DIM / BN);
    gemm_tf32<true,true,false,true><<<ge, TPB, SMEM_BYTES>>>(
        s2, we1, be1, s1, DIM, DIM, perm, tg, ts, tr, tc);
    gemm_tf32<true,false,true,false><<<ge, TPB, SMEM_BYTES>>>(
        s1, we2, be2, out, DIM, DIM, perm, tg, ts, tr, tc);
}

// round 15
// speedup vs baseline: 1.1020x; 1.0305x over previous
#include <cuda_runtime.h>
#include <cstdint>
#include <math.h>

// ---------------- problem constants ----------------
#define NGEN 10
#define BSZ  4096
#define INDIM 512
#define DIM  1024
#define MAX_TILES 48

// ---------------- scratch ----------------
__device__ float g_x [BSZ * INDIM];
__device__ float g_s1[BSZ * DIM];
__device__ float g_s2[BSZ * DIM];
__device__ float g_ws1[INDIM * DIM];
__device__ float g_ws2[DIM * DIM];
__device__ float g_we1[NGEN * DIM * DIM];
__device__ float g_we2[NGEN * DIM * DIM];
__device__ int   g_perm[BSZ];
__device__ int   g_tile_genre[MAX_TILES];
__device__ int   g_tile_start[MAX_TILES];
__device__ int   g_tile_rows [MAX_TILES];
__device__ int   g_tile_count;

// ---------------- helpers ----------------
__device__ __forceinline__ unsigned f2tf(float x) {
    unsigned r;
    asm("cvt.rna.tf32.f32 %0, %1;" : "=r"(r) : "f"(x));
    return r;
}
__device__ __forceinline__ float tfr(float x) {
    return __uint_as_float(f2tf(x));
}
__device__ __forceinline__ float gelu_f(float x) {
    return 0.5f * x * (1.0f + erff(x * 0.70710678118654752f));
}

// ---------------- tf32 pre-rounding ----------------
__global__ void round_w(const float4* __restrict__ s, float4* __restrict__ d, int n4) {
    int i = blockIdx.x * blockDim.x + threadIdx.x;
    if (i < n4) {
        float4 v = s[i];
        d[i] = make_float4(tfr(v.x), tfr(v.y), tfr(v.z), tfr(v.w));
    }
}

// fused rounding of Ws2 + We1 + We2 (side stream)
__global__ void round_all(const float4* __restrict__ s2w, float4* __restrict__ d2w, int n2,
                          const float4* __restrict__ e1s, float4* __restrict__ e1d,
                          const float4* __restrict__ e2s, float4* __restrict__ e2d, int n3) {
    int i = blockIdx.x * blockDim.x + threadIdx.x;
    const float4* s;
    float4* d;
    int j;
    if (i < n2)            { s = s2w; d = d2w; j = i; }
    else if (i < n2 + n3)  { s = e1s; d = e1d; j = i - n2; }
    else if (i < n2 + 2*n3){ s = e2s; d = e2d; j = i - n2 - n3; }
    else return;
    float4 v = s[j];
    d[j] = make_float4(tfr(v.x), tfr(v.y), tfr(v.z), tfr(v.w));
}

// ---------------- reparameterized sample (tf32-rounded output) -------------
__global__ void noise_kernel(const float4* __restrict__ mu,
                             const float4* __restrict__ sig,
                             const float4* __restrict__ z,
                             const int* __restrict__ genre,
                             float4* __restrict__ x) {
    const int C4 = INDIM / 4;
    int i = blockIdx.x * blockDim.x + threadIdx.x;
    if (i >= BSZ * C4) return;
    int row = i / C4, c = i - row * C4;
    int g = genre[row];
    float4 m = mu[g * C4 + c];
    float4 s = sig[g * C4 + c];
    float4 zz = z[i];
    float4 o;
    o.x = tfr(m.x + (fabsf(s.x) + 1e-8f) * zz.x);
    o.y = tfr(m.y + (fabsf(s.y) + 1e-8f) * zz.y);
    o.z = tfr(m.z + (fabsf(s.z) + 1e-8f) * zz.z);
    o.w = tfr(m.w + (fabsf(s.w) + 1e-8f) * zz.w);
    x[i] = o;
}

// ---------------- grouping (full tiles first, partial last) ----------------
__global__ void group_kernel(const int* __restrict__ genre) {
    __shared__ int cnt[256 * NGEN];
    __shared__ int tot[NGEN];
    __shared__ int base[NGEN];
    int t = threadIdx.x;
    const int per = BSZ / 256;

    int lc[NGEN];
#pragma unroll
    for (int g = 0; g < NGEN; g++) lc[g] = 0;
    int gr[per];
    for (int i = 0; i < per; i++) {
        int g = genre[t * per + i];
        gr[i] = g;
        lc[g]++;
    }
    for (int g = 0; g < NGEN; g++) cnt[t * NGEN + g] = lc[g];
    __syncthreads();

    if (t < NGEN) {
        int s = 0;
        for (int tt = 0; tt < 256; tt++) {
            int v = cnt[tt * NGEN + t];
            cnt[tt * NGEN + t] = s;
            s += v;
        }
        tot[t] = s;
    }
    __syncthreads();

    if (t == 0) {
        int off = 0;
        for (int g = 0; g < NGEN; g++) { base[g] = off; off += tot[g]; }
        int T = 0;
        int prows[NGEN], pstart[NGEN];
        for (int g = 0; g < NGEN; g++) {
            int c = tot[g], s0 = base[g];
            while (c >= 128) {
                g_tile_genre[T] = g;
                g_tile_start[T] = s0;
                g_tile_rows[T]  = 128;
                s0 += 128; c -= 128; T++;
            }
            prows[g] = c; pstart[g] = s0;
        }
        for (int g = 0; g < NGEN; g++) {
            if (prows[g] > 0) {
                g_tile_genre[T] = g;
                g_tile_start[T] = pstart[g];
                g_tile_rows[T]  = prows[g];
                T++;
            }
        }
        g_tile_count = T;
    }
    __syncthreads();

    int run[NGEN];
#pragma unroll
    for (int g = 0; g < NGEN; g++) run[g] = cnt[t * NGEN + g];
    for (int i = 0; i < per; i++) {
        int g = gr[i];
        int pos = base[g] + run[g]++;
        g_perm[pos] = t * per + i;
    }
}

// ------------- TF32 GEMM: cp.async 3-stage + ldmatrix, 2 CTAs/SM ------------
constexpr int BM = 128, BN = 128, BK = 32, TPB = 256;
constexpr int A_SW = 36;
constexpr int A_STG = BM * A_SW;             // 4608
constexpr int SB = 136;
constexpr int B_STG = BK * SB;               // 4352
constexpr int B0W = 3 * A_STG;               // 13824
constexpr int BIAS_W = B0W + 3 * B_STG;      // 26880
constexpr int SMEM_WORDS = BIAS_W + BN;      // 27008
constexpr int SMEM_BYTES = SMEM_WORDS * 4;   // 108032

__device__ __forceinline__ void cp16(uint32_t dst, const float* src) {
    asm volatile("cp.async.cg.shared.global [%0], [%1], 16;"
                 :: "r"(dst), "l"(src) : "memory");
}

template<bool EXPERT, bool GATHER_A, bool SCATTER_C, bool GELU>
__global__ void __launch_bounds__(TPB, 2)
gemm_tf32(const float* __restrict__ A, const float* __restrict__ Bw,
          const float* __restrict__ bias, float* __restrict__ C,
          int N, int K,
          const int* __restrict__ perm,
          const int* __restrict__ tgen, const int* __restrict__ tstart,
          const int* __restrict__ trows, const int* __restrict__ tcnt)
{
    extern __shared__ float sm[];

    int m0, rows, genre = 0, n0;
    if (EXPERT) {
        int tile = blockIdx.x;
        if (tile >= *tcnt) return;
        genre = tgen[tile];
        m0    = tstart[tile];
        rows  = trows[tile];
        n0    = blockIdx.y * BN;
    } else {
        m0 = blockIdx.x * BM;
        rows = BM;
        n0 = blockIdx.y * BN;
    }
    const float* Bsel = EXPERT ? Bw + (size_t)genre * K * N : Bw;
    const float* bsel = EXPERT ? bias + genre * N : bias;

    const int tid = threadIdx.x;
    if (tid < BN) sm[BIAS_W + tid] = bsel[n0 + tid];

    uint32_t smb;
    asm("{ .reg .u64 t; cvta.to.shared.u64 t, %1; cvt.u32.u64 %0, t; }"
        : "=r"(smb) : "l"(sm));

    // ---- A cp.async mapping ----
    const int row0 = tid >> 3;
    const int seg  = tid & 7;
    const float* aG[4];
    uint32_t awD[4];
#pragma unroll
    for (int i = 0; i < 4; i++) {
        int r = row0 + 32 * i;
        int lrc = r < rows ? r : (rows - 1);
        int src = m0 + lrc;
        if (GATHER_A) src = perm[src];
        aG[i]  = A + (size_t)src * K + seg * 4;
        awD[i] = (uint32_t)(r * A_SW + seg * 4) * 4;
    }
    // ---- B cp.async mapping ----
    const float* bG[4];
    uint32_t bwD[4];
#pragma unroll
    for (int j = 0; j < 4; j++) {
        int v = tid + TPB * j;
        int kB = v >> 5, n4 = v & 31;
        bG[j]  = Bsel + (size_t)kB * N + n0 + n4 * 4;
        bwD[j] = (uint32_t)(kB * SB + n4 * 4) * 4;
    }

    const int nk = K / BK;

    auto issue = [&](int kt) {
        const uint32_t as = smb + (uint32_t)((kt % 3) * A_STG) * 4;
        const uint32_t bs = smb + (uint32_t)(B0W + (kt % 3) * B_STG) * 4;
        const int ko = kt * BK;
#pragma unroll
        for (int i = 0; i < 4; i++) cp16(as + awD[i], aG[i] + ko);
#pragma unroll
        for (int j = 0; j < 4; j++) cp16(bs + bwD[j], bG[j] + (size_t)ko * N);
        asm volatile("cp.async.commit_group;" ::: "memory");
    };

    issue(0);
    issue(1);
    asm volatile("cp.async.wait_group 1;" ::: "memory");
    __syncthreads();

    // ---- compute mapping: 8 warps, warp tile 64x32 ----
    const int wid = tid >> 5, lane = tid & 31;
    const int wm = (wid >> 2) * 64;
    const int wn = (wid & 3) * 32;
    const int grp = lane >> 2, qid = lane & 3;
    const int mtBase = wm >> 4;
    const uint32_t lmOff = (uint32_t)(((lane & 15) * A_SW + (lane >> 4) * 4) * 4);

    bool mAct[4];
#pragma unroll
    for (int mt = 0; mt < 4; mt++) mAct[mt] = (wm + mt * 16) < rows;

    float acc[4][4][4];
#pragma unroll
    for (int i = 0; i < 4; i++)
#pragma unroll
        for (int j = 0; j < 4; j++)
#pragma unroll
            for (int q = 0; q < 4; q++) acc[i][j][q] = 0.f;

    for (int kt = 0; kt < nk; kt++) {
        if (kt + 2 < nk) issue(kt + 2);

        const uint32_t asB = smb + (uint32_t)((kt % 3) * A_STG) * 4;
        const int bsW = B0W + (kt % 3) * B_STG;
#pragma unroll
        for (int ks = 0; ks < 4; ks++) {
            uint32_t a[4][4];
#pragma unroll
            for (int mt = 0; mt < 4; mt++) {
                if (mAct[mt]) {
                    uint32_t ad = asB + lmOff + (uint32_t)((mtBase + mt) * 16 * A_SW * 4 + ks * 32);
                    asm volatile(
                        "ldmatrix.sync.aligned.m8n8.x4.shared.b16 {%0,%1,%2,%3}, [%4];"
                        : "=r"(a[mt][0]), "=r"(a[mt][1]), "=r"(a[mt][2]), "=r"(a[mt][3])
                        : "r"(ad));
                }
            }
            unsigned bfr[4][2];
#pragma unroll
            for (int nt = 0; nt < 4; nt++) {
                int col = wn + nt * 8 + grp;
                bfr[nt][0] = __float_as_uint(sm[bsW + (ks * 8 + qid) * SB + col]);
                bfr[nt][1] = __float_as_uint(sm[bsW + (ks * 8 + qid + 4) * SB + col]);
            }
#pragma unroll
            for (int mt = 0; mt < 4; mt++) {
                if (!mAct[mt]) continue;
#pragma unroll
                for (int nt = 0; nt < 4; nt++) {
                    float* d = acc[mt][nt];
                    asm volatile(
                        "mma.sync.aligned.m16n8k8.row.col.f32.tf32.tf32.f32 "
                        "{%0,%1,%2,%3},{%4,%5,%6,%7},{%8,%9},{%0,%1,%2,%3};\n"
                        : "+f"(d[0]), "+f"(d[1]), "+f"(d[2]), "+f"(d[3])
                        : "r"(a[mt][0]), "r"(a[mt][1]), "r"(a[mt][2]), "r"(a[mt][3]),
                          "r"(bfr[nt][0]), "r"(bfr[nt][1]));
                }
            }
        }
        if (kt + 1 < nk) {
            if (kt + 2 < nk) {
                asm volatile("cp.async.wait_group 1;" ::: "memory");
            } else {
                asm volatile("cp.async.wait_group 0;" ::: "memory");
            }
        }
        __syncthreads();
    }

    // ---- epilogue ----
#pragma unroll
    for (int mt = 0; mt < 4; mt++) {
#pragma unroll
        for (int h = 0; h < 2; h++) {
            int rl = wm + mt * 16 + grp + 8 * h;
            if (rl < rows) {
                int orow = m0 + rl;
                if (SCATTER_C) orow = perm[orow];
                float* crow = C + (size_t)orow * N + n0 + wn;
#pragma unroll
                for (int nt = 0; nt < 4; nt++) {
                    int c = nt * 8 + 2 * qid;
                    float x0 = acc[mt][nt][2 * h + 0] + sm[BIAS_W + wn + c];
                    float x1 = acc[mt][nt][2 * h + 1] + sm[BIAS_W + wn + c + 1];
                    if (GELU) {
                        x0 = tfr(gelu_f(x0));
                        x1 = tfr(gelu_f(x1));
                    }
                    *(float2*)(crow + c) = make_float2(x0, x1);
                }
            }
        }
    }
}

// ---------------- launcher ----------------
extern "C" void kernel_launch(void* const* d_in, const int* in_sizes, int n_in,
                              void* d_out, int out_size) {
    const int*   genre = (const int*)  d_in[1];
    const float* z     = (const float*)d_in[2];
    const float* mu    = (const float*)d_in[3];
    const float* sigma = (const float*)d_in[4];
    const float* Ws1   = (const float*)d_in[5];
    const float* bs1   = (const float*)d_in[6];
    const float* Ws2   = (const float*)d_in[7];
    const float* bs2   = (const float*)d_in[8];
    const float* We1   = (const float*)d_in[9];
    const float* be1   = (const float*)d_in[10];
    const float* We2   = (const float*)d_in[11];
    const float* be2   = (const float*)d_in[12];
    float* out = (float*)d_out;

    void *px, *ps1, *ps2, *pw1, *pw2, *pe1, *pe2, *pperm, *ptg, *pts, *ptr_, *ptc;
    cudaGetSymbolAddress(&px,   g_x);
    cudaGetSymbolAddress(&ps1,  g_s1);
    cudaGetSymbolAddress(&ps2,  g_s2);
    cudaGetSymbolAddress(&pw1,  g_ws1);
    cudaGetSymbolAddress(&pw2,  g_ws2);
    cudaGetSymbolAddress(&pe1,  g_we1);
    cudaGetSymbolAddress(&pe2,  g_we2);
    cudaGetSymbolAddress(&pperm, g_perm);
    cudaGetSymbolAddress(&ptg,  g_tile_genre);
    cudaGetSymbolAddress(&pts,  g_tile_start);
    cudaGetSymbolAddress(&ptr_, g_tile_rows);
    cudaGetSymbolAddress(&ptc,  g_tile_count);
    float* x   = (float*)px;
    float* s1  = (float*)ps1;
    float* s2  = (float*)ps2;
    float* ws1 = (float*)pw1;
    float* ws2 = (float*)pw2;
    float* we1 = (float*)pe1;
    float* we2 = (float*)pe2;
    const int* perm = (const int*)pperm;
    const int* tg = (const int*)ptg;
    const int* ts = (const int*)pts;
    const int* tr = (const int*)ptr_;
    const int* tc = (const int*)ptc;

    cudaFuncSetAttribute(gemm_tf32<false,false,false,true>,
                         cudaFuncAttributeMaxDynamicSharedMemorySize, SMEM_BYTES);
    cudaFuncSetAttribute(gemm_tf32<true,true,false,true>,
                         cudaFuncAttributeMaxDynamicSharedMemorySize, SMEM_BYTES);
    cudaFuncSetAttribute(gemm_tf32<true,false,true,false>,
                         cudaFuncAttributeMaxDynamicSharedMemorySize, SMEM_BYTES);

    // ONE side stream + three events (round-13-proven memory footprint:
    // the 2MB teardown leak in round 14 came from the SECOND stream)
    cudaStream_t sW;
    cudaEvent_t evFork, evW, evG;
    cudaStreamCreateWithFlags(&sW, cudaStreamNonBlocking);
    cudaEventCreateWithFlags(&evFork, cudaEventDisableTiming);
    cudaEventCreateWithFlags(&evW, cudaEventDisableTiming);
    cudaEventCreateWithFlags(&evG, cudaEventDisableTiming);

    // fork: side stream does round_all (ws2/we1/we2) then group_kernel
    cudaEventRecord(evFork, 0);
    {
        int n2 = DIM * DIM / 4;
        int n3 = NGEN * DIM * DIM / 4;
        cudaStreamWaitEvent(sW, evFork, 0);
        int total = n2 + 2 * n3;
        round_all<<<(total + 255) / 256, 256, 0, sW>>>(
            (const float4*)Ws2, (float4*)ws2, n2,
            (const float4*)We1, (float4*)we1,
            (const float4*)We2, (float4*)we2, n3);
        cudaEventRecord(evW, sW);
        group_kernel<<<1, 256, 0, sW>>>(genre);
        cudaEventRecord(evG, sW);
    }

    // main stream: round Ws1 -> noise -> L1
    round_w<<<(INDIM * DIM / 4 + 255) / 256, 256>>>(
        (const float4*)Ws1, (float4*)ws1, INDIM * DIM / 4);
    {
        int total = BSZ * INDIM / 4;
        noise_kernel<<<(total + 255) / 256, 256>>>(
            (const float4*)mu, (const float4*)sigma, (const float4*)z, genre, (float4*)x);
    }

    dim3 gs(BSZ / BM, DIM / BN);
    gemm_tf32<false,false,false,true><<<gs, TPB, SMEM_BYTES>>>(
        x, ws1, bs1, s1, DIM, INDIM, nullptr, nullptr, nullptr, nullptr, nullptr);

    // join W: ws2/we1/we2 ready
    cudaStreamWaitEvent(0, evW, 0);

    gemm_tf32<false,false,false,true><<<gs, TPB, SMEM_BYTES>>>(
        s1, ws2, bs2, s2, DIM, DIM, nullptr, nullptr, nullptr, nullptr, nullptr);

    // join G: perm/tiles ready (group finished on side stream long before)
    cudaStreamWaitEvent(0, evG, 0);

    // expert layers
    dim3 ge(MAX_TILES, DIM / BN);
    gemm_tf32<true,true,false,true><<<ge, TPB, SMEM_BYTES>>>(
        s2, we1, be1, s1, DIM, DIM, perm, tg, ts, tr, tc);
    gemm_tf32<true,false,true,false><<<ge, TPB, SMEM_BYTES>>>(
        s1, we2, be2, out, DIM, DIM, perm, tg, ts, tr, tc);
}